// round 5
// baseline (speedup 1.0000x reference)
#include <cuda_runtime.h>
#include <cuda_bf16.h>
#include <cstdint>
#include <math.h>

// QuantumNet fused, round 5: one thread per row (warp-uniform broadcast
// weight LDS) + register double-buffered direct LDG.128 x-stream.
// No tile barriers, no cp.async — MLP comes from unrolled reg ping-pong.

#define KDIM 512
#define THREADS 64

__global__ __launch_bounds__(THREADS)
void qnet_kernel(const float* __restrict__ x,
                 const float* __restrict__ pre_w,
                 const float* __restrict__ pre_b,
                 const float* __restrict__ u3p,
                 const float* __restrict__ post_w,
                 const float* __restrict__ post_b,
                 float* __restrict__ out, int B)
{
    __shared__ float wts[KDIM * 4];   // [k][q] transposed, 8 KB

    #pragma unroll
    for (int i = threadIdx.x; i < KDIM * 4; i += THREADS) {
        int q = i >> 9;
        int k = i & (KDIM - 1);
        wts[k * 4 + q] = pre_w[i];
    }
    __syncthreads();

    const int row = blockIdx.x * THREADS + threadIdx.x;
    if (row >= B) return;

    const float4* __restrict__ xr = (const float4*)(x + (size_t)row * KDIM);

    float a0 = 0.f, a1 = 0.f, a2 = 0.f, a3 = 0.f;
    float4 bufA[8], bufB[8];

    #pragma unroll
    for (int j = 0; j < 8; ++j) bufA[j] = __ldg(&xr[j]);

    #pragma unroll
    for (int t = 0; t < 16; ++t) {       // 16 blocks x 8 float4 = 128 float4
        float4* cur = (t & 1) ? bufB : bufA;   // compile-time after unroll
        float4* nxt = (t & 1) ? bufA : bufB;
        if (t < 15) {
            #pragma unroll
            for (int j = 0; j < 8; ++j)
                nxt[j] = __ldg(&xr[(t + 1) * 8 + j]);
        }
        #pragma unroll
        for (int j = 0; j < 8; ++j) {
            float4 xv = cur[j];
            const int k = t * 32 + j * 4;             // uniform across warp
            float4 w0 = *(const float4*)&wts[(k + 0) * 4];
            float4 w1 = *(const float4*)&wts[(k + 1) * 4];
            float4 w2 = *(const float4*)&wts[(k + 2) * 4];
            float4 w3 = *(const float4*)&wts[(k + 3) * 4];
            a0 = fmaf(xv.x, w0.x, a0); a1 = fmaf(xv.x, w0.y, a1);
            a2 = fmaf(xv.x, w0.z, a2); a3 = fmaf(xv.x, w0.w, a3);
            a0 = fmaf(xv.y, w1.x, a0); a1 = fmaf(xv.y, w1.y, a1);
            a2 = fmaf(xv.y, w1.z, a2); a3 = fmaf(xv.y, w1.w, a3);
            a0 = fmaf(xv.z, w2.x, a0); a1 = fmaf(xv.z, w2.y, a1);
            a2 = fmaf(xv.z, w2.z, a2); a3 = fmaf(xv.z, w2.w, a3);
            a0 = fmaf(xv.w, w3.x, a0); a1 = fmaf(xv.w, w3.y, a1);
            a2 = fmaf(xv.w, w3.z, a2); a3 = fmaf(xv.w, w3.w, a3);
        }
    }

    float pre[4];
    pre[0] = a0 + pre_b[0];
    pre[1] = a1 + pre_b[1];
    pre[2] = a2 + pre_b[2];
    pre[3] = a3 + pre_b[3];

    // Per-qubit state after H, RY(atan t), RZ(atan t^2):
    //   alpha = (c-s)/sqrt2 e^{-i rz/2}, beta = (c+s)/sqrt2 e^{+i rz/2}
    float aR[4], aI[4], bR[4], bI[4];
    const float HALF_PI = 1.5707963267948966f;
    const float INV_SQRT2 = 0.7071067811865476f;
    #pragma unroll
    for (int q = 0; q < 4; ++q) {
        float t  = tanhf(pre[q] * 0.1f) * HALF_PI;
        float cr = rsqrtf(fmaf(t, t, 1.f));
        float sr = t * cr;
        float c2 = sqrtf(0.5f * (1.f + cr));
        float s2 = 0.5f * sr * __fdividef(1.f, c2);
        float u  = t * t;
        float cz = rsqrtf(fmaf(u, u, 1.f));
        float szf = u * cz;
        float ch = sqrtf(0.5f * (1.f + cz));
        float sh = 0.5f * szf * __fdividef(1.f, ch);
        float Aa = (c2 - s2) * INV_SQRT2;
        float Bb = (c2 + s2) * INV_SQRT2;
        aR[q] = Aa * ch;  aI[q] = -Aa * sh;
        bR[q] = Bb * ch;  bI[q] =  Bb * sh;
    }

    float tR[4], tI[4], uR[4], uI[4];
    #pragma unroll
    for (int h = 0; h < 4; ++h) {
        int j0 = h >> 1, j1 = h & 1;
        float r0 = j0 ? bR[0] : aR[0], i0 = j0 ? bI[0] : aI[0];
        float r1 = j1 ? bR[1] : aR[1], i1 = j1 ? bI[1] : aI[1];
        tR[h] = r0 * r1 - i0 * i1;
        tI[h] = r0 * i1 + i0 * r1;
        float r2 = j0 ? bR[2] : aR[2], i2 = j0 ? bI[2] : aI[2];
        float r3 = j1 ? bR[3] : aR[3], i3 = j1 ? bI[3] : aI[3];
        uR[h] = r2 * r3 - i2 * i3;
        uI[h] = r2 * i3 + i2 * r3;
    }

    // Post-CNOT state via compile-time GF(2) permutation
    float AR[16], AI[16], NR[16];
    #pragma unroll
    for (int i = 0; i < 16; ++i) {
        int a_ = (i >> 3) & 1, b_ = (i >> 2) & 1, c_ = (i >> 1) & 1, d_ = i & 1;
        int s  = ((a_ ^ b_ ^ c_) << 3) | ((a_ ^ c_ ^ d_) << 2)
               | ((a_ ^ b_ ^ d_) << 1) | (a_ ^ b_);
        int hi = s >> 2, lo = s & 3;
        AR[i] = tR[hi] * uR[lo] - tI[hi] * uI[lo];
        AI[i] = tR[hi] * uI[lo] + tI[hi] * uR[lo];
        NR[i] = AR[i] * AR[i] + AI[i] * AI[i];
    }

    // U3 folded into M_q = U3^dag Z U3
    float ct4[4], mr4[4], mi4[4];
    #pragma unroll
    for (int q = 0; q < 4; ++q) {
        float th = u3p[q * 3 + 0];
        float la = u3p[q * 3 + 2];
        float st_, ct_, sl_, cl_;
        __sincosf(th, &st_, &ct_);
        __sincosf(la, &sl_, &cl_);
        ct4[q] = ct_;
        mr4[q] = -st_ * cl_;
        mi4[q] = -st_ * sl_;
    }

    float E[4];
    #pragma unroll
    for (int q = 0; q < 4; ++q) {
        const int p = 3 - q;
        float Sn = 0.f, Szr = 0.f, Szi = 0.f;
        #pragma unroll
        for (int m = 0; m < 8; ++m) {
            int lowmask = (1 << p) - 1;
            int i0 = ((m & ~lowmask) << 1) | (m & lowmask);
            int i1 = i0 | (1 << p);
            Sn  += NR[i0] - NR[i1];
            Szr += AR[i0] * AR[i1] + AI[i0] * AI[i1];
            Szi += AR[i0] * AI[i1] - AI[i0] * AR[i1];
        }
        E[q] = ct4[q] * Sn + 2.f * (mr4[q] * Szr - mi4[q] * Szi);
    }

    float o0 = post_b[0], o1 = post_b[1];
    #pragma unroll
    for (int q = 0; q < 4; ++q) {
        o0 = fmaf(post_w[q],     E[q], o0);
        o1 = fmaf(post_w[4 + q], E[q], o1);
    }
    float2 res; res.x = o0; res.y = o1;
    ((float2*)out)[row] = res;
}

extern "C" void kernel_launch(void* const* d_in, const int* in_sizes, int n_in,
                              void* d_out, int out_size) {
    const float* x      = (const float*)d_in[0];
    const float* pre_w  = (const float*)d_in[1];
    const float* pre_b  = (const float*)d_in[2];
    const float* u3p    = (const float*)d_in[3];
    const float* post_w = (const float*)d_in[4];
    const float* post_b = (const float*)d_in[5];
    float* out = (float*)d_out;

    int B = in_sizes[0] / KDIM;
    int grid = (B + THREADS - 1) / THREADS;
    qnet_kernel<<<grid, THREADS>>>(x, pre_w, pre_b, u3p, post_w, post_b, out, B);
}

// round 6
// speedup vs baseline: 1.3006x; 1.3006x over previous
#include <cuda_runtime.h>
#include <cuda_bf16.h>
#include <cstdint>
#include <math.h>

// QuantumNet fused, round 6: R3 structure (coalesced cp.async tiles,
// warp-uniform broadcast weight LDS) with pipeline depth 3 instead of 2.

#define KDIM 512
#define ROWS 64
#define THREADS 64
#define KTILE 64
#define NTILES (KDIM / KTILE)   // 8
#define NSTAGES 3
#define XS_STRIDE 68            // 64 + 4 pad

__device__ __forceinline__ void cpasync16(float* dst_smem, const float* src) {
    unsigned int s = (unsigned int)__cvta_generic_to_shared(dst_smem);
    asm volatile("cp.async.cg.shared.global [%0], [%1], 16;\n" :: "r"(s), "l"(src));
}

__global__ __launch_bounds__(THREADS)
void qnet_kernel(const float* __restrict__ x,
                 const float* __restrict__ pre_w,
                 const float* __restrict__ pre_b,
                 const float* __restrict__ u3p,
                 const float* __restrict__ post_w,
                 const float* __restrict__ post_b,
                 float* __restrict__ out, int B)
{
    __shared__ float wts[KDIM * 4];                    // 8 KB
    __shared__ float xs[NSTAGES][ROWS * XS_STRIDE];    // 3 x 17.4 KB

    const int tid  = threadIdx.x;
    const int row0 = blockIdx.x * ROWS;
    const int row  = row0 + tid;

    #pragma unroll
    for (int i = tid; i < KDIM * 4; i += THREADS) {
        int q = i >> 9;
        int k = i & (KDIM - 1);
        wts[k * 4 + q] = pre_w[i];
    }

    auto issue_tile = [&](int kt, int stage) {
        const int kbase = kt * KTILE;
        #pragma unroll
        for (int i = 0; i < 16; ++i) {
            int f = tid + i * THREADS;   // 0..1023
            int r = f >> 4;              // row 0..63
            int c = f & 15;              // float4 col
            int gr = row0 + r;
            if (gr < B)
                cpasync16(&xs[stage][r * XS_STRIDE + c * 4],
                          &x[(size_t)gr * KDIM + kbase + c * 4]);
        }
        asm volatile("cp.async.commit_group;\n" ::);
    };

    issue_tile(0, 0);
    issue_tile(1, 1);
    issue_tile(2, 2);

    float acc0 = 0.f, acc1 = 0.f, acc2 = 0.f, acc3 = 0.f;

    #pragma unroll
    for (int kt = 0; kt < NTILES; ++kt) {
        // outstanding groups after this wait: min(NTILES-1-kt, NSTAGES-1)
        if (kt < NTILES - 2)
            asm volatile("cp.async.wait_group 2;\n" ::);
        else if (kt == NTILES - 2)
            asm volatile("cp.async.wait_group 1;\n" ::);
        else
            asm volatile("cp.async.wait_group 0;\n" ::);
        __syncthreads();

        const int stage = kt % NSTAGES;
        const int kbase = kt * KTILE;
        #pragma unroll
        for (int k = 0; k < KTILE; k += 4) {
            float4 xv = *(const float4*)&xs[stage][tid * XS_STRIDE + k];
            float4 w0 = *(const float4*)&wts[(kbase + k + 0) * 4];
            float4 w1 = *(const float4*)&wts[(kbase + k + 1) * 4];
            float4 w2 = *(const float4*)&wts[(kbase + k + 2) * 4];
            float4 w3 = *(const float4*)&wts[(kbase + k + 3) * 4];
            acc0 = fmaf(xv.x, w0.x, acc0); acc1 = fmaf(xv.x, w0.y, acc1);
            acc2 = fmaf(xv.x, w0.z, acc2); acc3 = fmaf(xv.x, w0.w, acc3);
            acc0 = fmaf(xv.y, w1.x, acc0); acc1 = fmaf(xv.y, w1.y, acc1);
            acc2 = fmaf(xv.y, w1.z, acc2); acc3 = fmaf(xv.y, w1.w, acc3);
            acc0 = fmaf(xv.z, w2.x, acc0); acc1 = fmaf(xv.z, w2.y, acc1);
            acc2 = fmaf(xv.z, w2.z, acc2); acc3 = fmaf(xv.z, w2.w, acc3);
            acc0 = fmaf(xv.w, w3.x, acc0); acc1 = fmaf(xv.w, w3.y, acc1);
            acc2 = fmaf(xv.w, w3.z, acc2); acc3 = fmaf(xv.w, w3.w, acc3);
        }
        __syncthreads();   // stage fully consumed

        if (kt + NSTAGES < NTILES)
            issue_tile(kt + NSTAGES, stage);
    }

    if (row >= B) return;

    float pre[4];
    pre[0] = acc0 + pre_b[0];
    pre[1] = acc1 + pre_b[1];
    pre[2] = acc2 + pre_b[2];
    pre[3] = acc3 + pre_b[3];

    // Per-qubit state after H, RY(atan t), RZ(atan t^2)
    float aR[4], aI[4], bR[4], bI[4];
    const float HALF_PI = 1.5707963267948966f;
    const float INV_SQRT2 = 0.7071067811865476f;
    #pragma unroll
    for (int q = 0; q < 4; ++q) {
        float t  = tanhf(pre[q] * 0.1f) * HALF_PI;
        float cr = rsqrtf(fmaf(t, t, 1.f));
        float sr = t * cr;
        float c2 = sqrtf(0.5f * (1.f + cr));
        float s2 = 0.5f * sr * __fdividef(1.f, c2);
        float u  = t * t;
        float cz = rsqrtf(fmaf(u, u, 1.f));
        float szf = u * cz;
        float ch = sqrtf(0.5f * (1.f + cz));
        float sh = 0.5f * szf * __fdividef(1.f, ch);
        float Aa = (c2 - s2) * INV_SQRT2;
        float Bb = (c2 + s2) * INV_SQRT2;
        aR[q] = Aa * ch;  aI[q] = -Aa * sh;
        bR[q] = Bb * ch;  bI[q] =  Bb * sh;
    }

    float tR[4], tI[4], uR[4], uI[4];
    #pragma unroll
    for (int h = 0; h < 4; ++h) {
        int j0 = h >> 1, j1 = h & 1;
        float r0 = j0 ? bR[0] : aR[0], i0 = j0 ? bI[0] : aI[0];
        float r1 = j1 ? bR[1] : aR[1], i1 = j1 ? bI[1] : aI[1];
        tR[h] = r0 * r1 - i0 * i1;
        tI[h] = r0 * i1 + i0 * r1;
        float r2 = j0 ? bR[2] : aR[2], i2 = j0 ? bI[2] : aI[2];
        float r3 = j1 ? bR[3] : aR[3], i3 = j1 ? bI[3] : aI[3];
        uR[h] = r2 * r3 - i2 * i3;
        uI[h] = r2 * i3 + i2 * r3;
    }

    float AR[16], AI[16], NR[16];
    #pragma unroll
    for (int i = 0; i < 16; ++i) {
        int a_ = (i >> 3) & 1, b_ = (i >> 2) & 1, c_ = (i >> 1) & 1, d_ = i & 1;
        int s  = ((a_ ^ b_ ^ c_) << 3) | ((a_ ^ c_ ^ d_) << 2)
               | ((a_ ^ b_ ^ d_) << 1) | (a_ ^ b_);
        int hi = s >> 2, lo = s & 3;
        AR[i] = tR[hi] * uR[lo] - tI[hi] * uI[lo];
        AI[i] = tR[hi] * uI[lo] + tI[hi] * uR[lo];
        NR[i] = AR[i] * AR[i] + AI[i] * AI[i];
    }

    float ct4[4], mr4[4], mi4[4];
    #pragma unroll
    for (int q = 0; q < 4; ++q) {
        float th = u3p[q * 3 + 0];
        float la = u3p[q * 3 + 2];
        float st_, ct_, sl_, cl_;
        __sincosf(th, &st_, &ct_);
        __sincosf(la, &sl_, &cl_);
        ct4[q] = ct_;
        mr4[q] = -st_ * cl_;
        mi4[q] = -st_ * sl_;
    }

    float E[4];
    #pragma unroll
    for (int q = 0; q < 4; ++q) {
        const int p = 3 - q;
        float Sn = 0.f, Szr = 0.f, Szi = 0.f;
        #pragma unroll
        for (int m = 0; m < 8; ++m) {
            int lowmask = (1 << p) - 1;
            int i0 = ((m & ~lowmask) << 1) | (m & lowmask);
            int i1 = i0 | (1 << p);
            Sn  += NR[i0] - NR[i1];
            Szr += AR[i0] * AR[i1] + AI[i0] * AI[i1];
            Szi += AR[i0] * AI[i1] - AI[i0] * AR[i1];
        }
        E[q] = ct4[q] * Sn + 2.f * (mr4[q] * Szr - mi4[q] * Szi);
    }

    float o0 = post_b[0], o1 = post_b[1];
    #pragma unroll
    for (int q = 0; q < 4; ++q) {
        o0 = fmaf(post_w[q],     E[q], o0);
        o1 = fmaf(post_w[4 + q], E[q], o1);
    }
    float2 res; res.x = o0; res.y = o1;
    ((float2*)out)[row] = res;
}

extern "C" void kernel_launch(void* const* d_in, const int* in_sizes, int n_in,
                              void* d_out, int out_size) {
    const float* x      = (const float*)d_in[0];
    const float* pre_w  = (const float*)d_in[1];
    const float* pre_b  = (const float*)d_in[2];
    const float* u3p    = (const float*)d_in[3];
    const float* post_w = (const float*)d_in[4];
    const float* post_b = (const float*)d_in[5];
    float* out = (float*)d_out;

    int B = in_sizes[0] / KDIM;
    int grid = (B + ROWS - 1) / ROWS;
    qnet_kernel<<<grid, THREADS>>>(x, pre_w, pre_b, u3p, post_w, post_b, out, B);
}